// round 1
// baseline (speedup 1.0000x reference)
#include <cuda_runtime.h>
#include <cstdint>

#define HID 128
#define NB 50000
#define NC 2500
#define NLAYERS 2
#define NBF (NB*HID)
#define NCF (NC*HID)

typedef unsigned long long u64;

// ---------- packed f32x2 helpers (FFMA2 only reachable via PTX) ----------
__device__ __forceinline__ u64 pack2(float x, float y){
    u64 d; asm("mov.b64 %0, {%1, %2};" : "=l"(d) : "f"(x), "f"(y)); return d;
}
__device__ __forceinline__ float2 unpack2(u64 d){
    float2 v; asm("mov.b64 {%0, %1}, %2;" : "=f"(v.x), "=f"(v.y) : "l"(d)); return v;
}
__device__ __forceinline__ u64 fma2(u64 a, u64 b, u64 c){
    u64 d; asm("fma.rn.f32x2 %0, %1, %2, %3;" : "=l"(d) : "l"(a), "l"(b), "l"(c)); return d;
}
__device__ __forceinline__ float gelu_f(float x){
    return 0.5f * x * (1.0f + erff(x * 0.70710678118654752440f));
}
__device__ __forceinline__ void red_add_v4(float* p, float a, float b, float c, float d){
    asm volatile("red.global.add.v4.f32 [%0], {%1, %2, %3, %4};"
                 :: "l"(p), "f"(a), "f"(b), "f"(c), "f"(d) : "memory");
}

#define SA_STRIDE 132   // 128 + 4 pad: conflict-free A-tile column reads
#define SMEM_BYTES ((64*SA_STRIDE + HID*HID)*4)

// ---------- shared GEMM mainloop: C(64x128) tile, K=128 ----------
// thread t: tr=t/16 owns rows r0=4*tr..+3 ; tc=t%16 owns cols {4tc..4tc+3, 4tc+64..4tc+67}
__device__ __forceinline__ void load_W_smem(const float* __restrict__ W, float* sW, int t){
    const float4* W4 = reinterpret_cast<const float4*>(W);
    float4* s4 = reinterpret_cast<float4*>(sW);
    #pragma unroll
    for (int i = 0; i < 16; i++) s4[t + 256*i] = W4[t + 256*i];
}

__device__ __forceinline__ void gemm_mainloop(const float* sW, const float* sA,
                                              int r0, int tc, u64 acc[4][2][2]){
    #pragma unroll
    for (int r=0;r<4;r++)
        #pragma unroll
        for (int j=0;j<2;j++){ acc[r][j][0]=0ULL; acc[r][j][1]=0ULL; }
    #pragma unroll 2
    for (int k0 = 0; k0 < HID; k0 += 4){
        float4 av[4];
        #pragma unroll
        for (int r=0;r<4;r++)
            av[r] = *reinterpret_cast<const float4*>(sA + (r0+r)*SA_STRIDE + k0);
        #pragma unroll
        for (int kk=0;kk<4;kk++){
            const float* wrow = sW + (k0+kk)*HID + 4*tc;
            ulonglong2 w0 = *reinterpret_cast<const ulonglong2*>(wrow);
            ulonglong2 w1 = *reinterpret_cast<const ulonglong2*>(wrow + 64);
            #pragma unroll
            for (int r=0;r<4;r++){
                float a = (kk==0)?av[r].x:(kk==1)?av[r].y:(kk==2)?av[r].z:av[r].w;
                u64 a2 = pack2(a, a);
                acc[r][0][0] = fma2(a2, w0.x, acc[r][0][0]);
                acc[r][0][1] = fma2(a2, w0.y, acc[r][0][1]);
                acc[r][1][0] = fma2(a2, w1.x, acc[r][1][0]);
                acc[r][1][1] = fma2(a2, w1.y, acc[r][1][1]);
            }
        }
    }
}

// ---------- out = [gelu]( (scale*X) @ W + b ), scale = 1 + *eps_ptr ----------
extern "C" __global__ void __launch_bounds__(256)
linear_kernel(const float* __restrict__ X, const float* __restrict__ W,
              const float* __restrict__ bias, float* __restrict__ out,
              int M, const float* __restrict__ eps_ptr, int do_gelu)
{
    extern __shared__ float smem[];
    float* sW = smem;
    float* sA = smem + HID*HID;
    int t = threadIdx.x;
    load_W_smem(W, sW, t);
    float scale = 1.0f;
    if (eps_ptr) scale = 1.0f + *eps_ptr;
    int row0 = blockIdx.x * 64;
    const float4* X4 = reinterpret_cast<const float4*>(X);
    #pragma unroll
    for (int i=0;i<8;i++){
        int idx = t + 256*i;
        int r = idx >> 5, c4 = idx & 31;
        float4 v = make_float4(0.f,0.f,0.f,0.f);
        if (row0 + r < M) v = X4[(size_t)(row0 + r)*32 + c4];
        v.x *= scale; v.y *= scale; v.z *= scale; v.w *= scale;
        *reinterpret_cast<float4*>(sA + r*SA_STRIDE + 4*c4) = v;
    }
    __syncthreads();
    int tr = t >> 4, tc = t & 15;
    int r0 = tr * 4;
    u64 acc[4][2][2];
    gemm_mainloop(sW, sA, r0, tc, acc);
    #pragma unroll
    for (int r=0;r<4;r++){
        int row = row0 + r0 + r;
        if (row >= M) continue;
        #pragma unroll
        for (int j=0;j<2;j++){
            int c = 4*tc + 64*j;
            float4 bv = *reinterpret_cast<const float4*>(bias + c);
            float2 v0 = unpack2(acc[r][j][0]);
            float2 v1 = unpack2(acc[r][j][1]);
            float o0 = v0.x + bv.x, o1 = v0.y + bv.y;
            float o2 = v1.x + bv.z, o3 = v1.y + bv.w;
            if (do_gelu){ o0=gelu_f(o0); o1=gelu_f(o1); o2=gelu_f(o2); o3=gelu_f(o3); }
            *reinterpret_cast<float4*>(out + (size_t)row*HID + c) = make_float4(o0,o1,o2,o3);
        }
    }
}

// ---------- fused edge kernel ----------
// acc = ea@We ; m = gelu(acc + be + xs[src]) * ew ; red.v4 into AGG[dst]
extern "C" __global__ void __launch_bounds__(256)
edge_kernel(const float* __restrict__ EA, const float* __restrict__ W,
            const float* __restrict__ bias, const int* __restrict__ ei,
            const float* __restrict__ ew, const float* __restrict__ XS,
            float* __restrict__ AGG, int E)
{
    extern __shared__ float smem[];
    float* sW = smem;
    float* sA = smem + HID*HID;
    int t = threadIdx.x;
    load_W_smem(W, sW, t);
    int e0 = blockIdx.x * 64;
    const float4* EA4 = reinterpret_cast<const float4*>(EA);
    #pragma unroll
    for (int i=0;i<8;i++){
        int idx = t + 256*i;
        int r = idx >> 5, c4 = idx & 31;
        float4 v = EA4[(size_t)(e0 + r)*32 + c4];
        *reinterpret_cast<float4*>(sA + r*SA_STRIDE + 4*c4) = v;
    }
    __syncthreads();
    int tr = t >> 4, tc = t & 15;
    int r0 = tr * 4;
    u64 acc[4][2][2];
    gemm_mainloop(sW, sA, r0, tc, acc);
    #pragma unroll
    for (int r=0;r<4;r++){
        int e = e0 + r0 + r;
        int src = ei[e];
        int dst = ei[E + e];
        float wgt = ew[e];
        #pragma unroll
        for (int j=0;j<2;j++){
            int c = 4*tc + 64*j;
            float4 bv = *reinterpret_cast<const float4*>(bias + c);
            float4 xv = *reinterpret_cast<const float4*>(XS + (size_t)src*HID + c);
            float2 v0 = unpack2(acc[r][j][0]);
            float2 v1 = unpack2(acc[r][j][1]);
            float m0 = gelu_f(v0.x + bv.x + xv.x) * wgt;
            float m1 = gelu_f(v0.y + bv.y + xv.y) * wgt;
            float m2 = gelu_f(v1.x + bv.z + xv.z) * wgt;
            float m3 = gelu_f(v1.y + bv.w + xv.w) * wgt;
            red_add_v4(AGG + (size_t)dst*HID + c, m0, m1, m2, m3);
        }
    }
}

// ---------- x += gelu(a + b) ----------
extern "C" __global__ void combine_kernel(float* __restrict__ x, const float* __restrict__ a,
                                          const float* __restrict__ b, int n){
    int i = blockIdx.x * blockDim.x + threadIdx.x;
    if (i < n) x[i] += gelu_f(a[i] + b[i]);
}

// ---------- scratch (no allocation allowed -> device global) ----------
__device__ float g_buf[(size_t)5*NBF + (size_t)5*NCF];

extern "C" void kernel_launch(void* const* d_in, const int* in_sizes, int n_in,
                              void* d_out, int out_size)
{
    (void)n_in; (void)out_size;
    const float* x_base = (const float*)d_in[0];
    const float* x_cent = (const float*)d_in[1];
    // edge-type order matches param index t: 0=bb 1=bc 2=cc 3=cb
    const int*   ei[4]  = {(const int*)d_in[2], (const int*)d_in[5], (const int*)d_in[8],  (const int*)d_in[11]};
    const float* ea[4]  = {(const float*)d_in[3], (const float*)d_in[6], (const float*)d_in[9],  (const float*)d_in[12]};
    const float* ewt[4] = {(const float*)d_in[4], (const float*)d_in[7], (const float*)d_in[10], (const float*)d_in[13]};
    const float* Wsrc = (const float*)d_in[14];
    const float* bsrc = (const float*)d_in[15];
    const float* Wdst = (const float*)d_in[16];
    const float* bdst = (const float*)d_in[17];
    const float* eps  = (const float*)d_in[18];
    const float* We   = (const float*)d_in[19];
    const float* be   = (const float*)d_in[20];
    const float* Wm1  = (const float*)d_in[21];
    const float* bm1  = (const float*)d_in[22];
    const float* Wm2  = (const float*)d_in[23];
    const float* bm2  = (const float*)d_in[24];

    float* base = nullptr;
    cudaGetSymbolAddress((void**)&base, g_buf);
    float* xb     = base;
    float* xs_bb  = base + (size_t)1*NBF;
    float* xs_bc  = base + (size_t)2*NBF;
    float* agg_bb = base + (size_t)3*NBF;
    float* agg_cb = base + (size_t)4*NBF;
    float* xc     = base + (size_t)5*NBF;
    float* xs_cc  = xc + (size_t)1*NCF;
    float* xs_cb  = xc + (size_t)2*NCF;
    float* agg_bc = xc + (size_t)3*NCF;
    float* agg_cc = xc + (size_t)4*NCF;

    cudaFuncSetAttribute((const void*)linear_kernel, cudaFuncAttributeMaxDynamicSharedMemorySize, SMEM_BYTES);
    cudaFuncSetAttribute((const void*)edge_kernel,   cudaFuncAttributeMaxDynamicSharedMemorySize, SMEM_BYTES);

    cudaMemcpyAsync(xb, x_base, sizeof(float)*(size_t)NBF, cudaMemcpyDeviceToDevice, 0);
    cudaMemcpyAsync(xc, x_cent, sizeof(float)*(size_t)NCF, cudaMemcpyDeviceToDevice, 0);

    for (int l = 0; l < NLAYERS; l++){
        #define WOFF(P,t) ((P) + ((size_t)l*4 + (t))*HID*HID)
        #define BOFF(P,t) ((P) + ((size_t)l*4 + (t))*HID)
        // lin_src per edge type (xs = x_src @ Wsrc + bsrc)
        linear_kernel<<<(NB+63)/64, 256, SMEM_BYTES>>>(xb, WOFF(Wsrc,0), BOFF(bsrc,0), xs_bb, NB, nullptr, 0);
        linear_kernel<<<(NB+63)/64, 256, SMEM_BYTES>>>(xb, WOFF(Wsrc,1), BOFF(bsrc,1), xs_bc, NB, nullptr, 0);
        linear_kernel<<<(NC+63)/64, 256, SMEM_BYTES>>>(xc, WOFF(Wsrc,2), BOFF(bsrc,2), xs_cc, NC, nullptr, 0);
        linear_kernel<<<(NC+63)/64, 256, SMEM_BYTES>>>(xc, WOFF(Wsrc,3), BOFF(bsrc,3), xs_cb, NC, nullptr, 0);
        // agg init with dst term: ((1+eps)*x_dst) @ Wdst + bdst
        linear_kernel<<<(NB+63)/64, 256, SMEM_BYTES>>>(xb, WOFF(Wdst,0), BOFF(bdst,0), agg_bb, NB, eps + l*4 + 0, 0);
        linear_kernel<<<(NB+63)/64, 256, SMEM_BYTES>>>(xb, WOFF(Wdst,3), BOFF(bdst,3), agg_cb, NB, eps + l*4 + 3, 0);
        linear_kernel<<<(NC+63)/64, 256, SMEM_BYTES>>>(xc, WOFF(Wdst,1), BOFF(bdst,1), agg_bc, NC, eps + l*4 + 1, 0);
        linear_kernel<<<(NC+63)/64, 256, SMEM_BYTES>>>(xc, WOFF(Wdst,2), BOFF(bdst,2), agg_cc, NC, eps + l*4 + 2, 0);
        // fused edge encode + message + scatter
        {
            const float* XSs[4]  = {xs_bb, xs_bc, xs_cc, xs_cb};
            float*       AGGs[4] = {agg_bb, agg_bc, agg_cc, agg_cb};
            for (int tt = 0; tt < 4; tt++){
                int E = in_sizes[4 + 3*tt];
                edge_kernel<<<E/64, 256, SMEM_BYTES>>>(ea[tt], WOFF(We,tt), BOFF(be,tt),
                                                       ei[tt], ewt[tt], XSs[tt], AGGs[tt], E);
            }
        }
        // MLP layer 1 (gelu) -> reuse xs buffers as temps
        linear_kernel<<<(NB+63)/64, 256, SMEM_BYTES>>>(agg_bb, WOFF(Wm1,0), BOFF(bm1,0), xs_bb, NB, nullptr, 1);
        linear_kernel<<<(NB+63)/64, 256, SMEM_BYTES>>>(agg_cb, WOFF(Wm1,3), BOFF(bm1,3), xs_bc, NB, nullptr, 1);
        linear_kernel<<<(NC+63)/64, 256, SMEM_BYTES>>>(agg_bc, WOFF(Wm1,1), BOFF(bm1,1), xs_cc, NC, nullptr, 1);
        linear_kernel<<<(NC+63)/64, 256, SMEM_BYTES>>>(agg_cc, WOFF(Wm1,2), BOFF(bm1,2), xs_cb, NC, nullptr, 1);
        // MLP layer 2 -> back into agg buffers
        linear_kernel<<<(NB+63)/64, 256, SMEM_BYTES>>>(xs_bb, WOFF(Wm2,0), BOFF(bm2,0), agg_bb, NB, nullptr, 0);
        linear_kernel<<<(NB+63)/64, 256, SMEM_BYTES>>>(xs_bc, WOFF(Wm2,3), BOFF(bm2,3), agg_cb, NB, nullptr, 0);
        linear_kernel<<<(NC+63)/64, 256, SMEM_BYTES>>>(xs_cc, WOFF(Wm2,1), BOFF(bm2,1), agg_bc, NC, nullptr, 0);
        linear_kernel<<<(NC+63)/64, 256, SMEM_BYTES>>>(xs_cb, WOFF(Wm2,2), BOFF(bm2,2), agg_cc, NC, nullptr, 0);
        // residual + gelu combine (HeteroConv sum of the two per-dst convs)
        combine_kernel<<<(NBF+255)/256, 256>>>(xb, agg_bb, agg_cb, NBF);
        combine_kernel<<<(NCF+255)/256, 256>>>(xc, agg_bc, agg_cc, NCF);
        #undef WOFF
        #undef BOFF
    }

    float* out = (float*)d_out;
    cudaMemcpyAsync(out,        xb, sizeof(float)*(size_t)NBF, cudaMemcpyDeviceToDevice, 0);
    cudaMemcpyAsync(out + NBF,  xc, sizeof(float)*(size_t)NCF, cudaMemcpyDeviceToDevice, 0);
}